// round 15
// baseline (speedup 1.0000x reference)
#include <cuda_runtime.h>
#include <cuda_fp16.h>
#include <cstdint>

#define BB 16
#define CC 768
#define TT 1024
#define STEPS 12
#define NNEG 10
#define COPIES 11
#define BT (BB*TT)  // 16384

// ---- scratch (static device globals; no runtime allocation) ----
__device__ __half g_yTh[(size_t)BB*TT*CC];        // [b][t][c] fp16
__device__ __half g_projh[(size_t)STEPS*BT*CC];   // [i][m][d] fp16
__device__ __half g_xh[(size_t)BT*CC];            // [m][c] fp16
__device__ __half g_wh[(size_t)STEPS*CC*CC];      // [(i*768+d)][c] fp16

// ============================ asm helpers ============================
__device__ __forceinline__ uint32_t smem_u32(const void* p) {
    uint32_t a;
    asm("{ .reg .u64 t; cvta.to.shared.u64 t, %1; cvt.u32.u64 %0, t; }" : "=r"(a) : "l"(p));
    return a;
}

__device__ __forceinline__ void cp_async16(uint32_t saddr, const void* gaddr) {
    asm volatile("cp.async.cg.shared.global [%0], [%1], 16;" :: "r"(saddr), "l"(gaddr));
}
__device__ __forceinline__ void cp_commit() {
    asm volatile("cp.async.commit_group;" ::: "memory");
}
__device__ __forceinline__ void cp_wait2() {
    asm volatile("cp.async.wait_group 2;" ::: "memory");
}

__device__ __forceinline__ void ldmx4(uint32_t* r, uint32_t addr) {
    asm volatile("ldmatrix.sync.aligned.m8n8.x4.shared.b16 {%0,%1,%2,%3}, [%4];"
        : "=r"(r[0]), "=r"(r[1]), "=r"(r[2]), "=r"(r[3]) : "r"(addr));
}

__device__ __forceinline__ void mma16816(float* d, const uint32_t* a, const uint32_t* b) {
    asm volatile("mma.sync.aligned.m16n8k16.row.col.f32.f16.f16.f32 "
        "{%0,%1,%2,%3}, {%4,%5,%6,%7}, {%8,%9}, {%0,%1,%2,%3};"
        : "+f"(d[0]), "+f"(d[1]), "+f"(d[2]), "+f"(d[3])
        : "r"(a[0]), "r"(a[1]), "r"(a[2]), "r"(a[3]), "r"(b[0]), "r"(b[1]));
}

// swizzled byte offset for a (row, 16B-chunk) of a [rows][32] fp16 tile
__device__ __forceinline__ uint32_t sw_off(int r, int c) {
    uint32_t bo = r*64 + c*16;
    return bo ^ (((bo >> 7) & 7) << 4);
}

// ============================ prepack kernels ============================
// fused x+y transpose -> fp16 [b][t][c]
__global__ void pack_xy_kernel(const float* __restrict__ x, const float* __restrict__ y) {
    __shared__ float tx_[32][33];
    __shared__ float ty_[32][33];
    int b = blockIdx.z, c0 = blockIdx.y * 32, t0 = blockIdx.x * 32;
    int tx = threadIdx.x, ty = threadIdx.y;
    #pragma unroll
    for (int j = 0; j < 32; j += 8) {
        size_t src = ((size_t)b*CC + c0 + ty + j)*TT + t0 + tx;
        tx_[ty + j][tx] = x[src];
        ty_[ty + j][tx] = y[src];
    }
    __syncthreads();
    #pragma unroll
    for (int j = 0; j < 32; j += 8) {
        size_t dst = ((size_t)b*TT + t0 + ty + j)*CC + c0 + tx;
        g_xh[dst]  = __float2half_rn(tx_[tx][ty + j]);
        g_yTh[dst] = __float2half_rn(ty_[tx][ty + j]);
    }
}

// W[c][d][i] -> g_wh[(i*768+d)][c], coalesced via padded smem transpose.
__global__ void pack_w_kernel(const float* __restrict__ W) {
    __shared__ __half sw[32][33][STEPS];
    const int c0 = blockIdx.x * 32, d0 = blockIdx.y * 32;
    const int tx = threadIdx.x, ty = threadIdx.y;
    #pragma unroll
    for (int j = 0; j < 4; j++) {
        int cl = ty + j*8;
        const float4* src = reinterpret_cast<const float4*>(
            W + ((size_t)(c0 + cl)*CC + d0 + tx)*STEPS);
        float4 a = src[0], bq = src[1], cq = src[2];
        __half* o = &sw[cl][tx][0];
        o[0] = __float2half_rn(a.x);  o[1] = __float2half_rn(a.y);
        o[2] = __float2half_rn(a.z);  o[3] = __float2half_rn(a.w);
        o[4] = __float2half_rn(bq.x); o[5] = __float2half_rn(bq.y);
        o[6] = __float2half_rn(bq.z); o[7] = __float2half_rn(bq.w);
        o[8] = __float2half_rn(cq.x); o[9] = __float2half_rn(cq.y);
        o[10] = __float2half_rn(cq.z); o[11] = __float2half_rn(cq.w);
    }
    __syncthreads();
    #pragma unroll
    for (int i = 0; i < STEPS; i++)
        #pragma unroll
        for (int j = 0; j < 4; j++) {
            int dl = ty + j*8;
            g_wh[((size_t)i*CC + d0 + dl)*CC + c0 + tx] = sw[tx][dl][i];
        }
}

// ============================ HMMA GEMM ============================
// Single-pass fp16: proj = x*w (+bias), output fp16.
// Tile 128x256x32, 256 thr (2x4 warps, warp=64x64), 4-stage cp.async.
// Warp tile 64x64 -> 32 FLOP/smem-byte (was 21): attacks the LDSM bound.
#define BM 128
#define BN 256
#define BK 32
#define KITERS (CC/BK)     // 24
#define A_BYTES (BM*BK*2)  // 8192
#define B_BYTES (BN*BK*2)  // 16384
#define SA_H 0
#define SB_H A_BYTES
#define STG  (A_BYTES + B_BYTES)  // 24576 per stage
#define NSTG 4
#define SMEM_GEMM (NSTG*STG)      // 98304

__global__ __launch_bounds__(256, 1) void gemm_hmma_kernel(const float* __restrict__ bias)
{
    extern __shared__ char smem[];
    const uint32_t sbase = smem_u32(smem);
    const int tid = threadIdx.x;
    const int wid = tid >> 5, lane = tid & 31;
    const int n0 = blockIdx.x * BN;
    const int m0 = blockIdx.y * BM;
    const int stepi = blockIdx.z;
    const int wm = wid >> 2;     // 0..1  (64 rows)
    const int wn = wid & 3;      // 0..3  (64 cols)

    const __half* gA = g_xh + (size_t)m0*CC;
    const __half* gB = g_wh + ((size_t)stepi*CC + n0)*CC;

    const int lr0 = tid >> 2, lc = tid & 3;

    auto load_stage = [&](int kt, int s) {
        const int k0 = kt * BK;
        const uint32_t sa = sbase + s*STG;
        #pragma unroll
        for (int e = 0; e < 2; e++) {        // A: 128 rows x 4 chunks
            int r = lr0 + e*64;
            uint32_t so = sw_off(r, lc);
            size_t go = (size_t)r*CC + k0 + lc*8;
            cp_async16(sa + SA_H + so, gA + go);
        }
        #pragma unroll
        for (int e = 0; e < 4; e++) {        // B: 256 rows x 4 chunks
            int idx = tid + e*256;
            int r = idx >> 2, c = idx & 3;
            uint32_t so = sw_off(r, c);
            size_t go = (size_t)r*CC + k0 + c*8;
            cp_async16(sa + SB_H + so, gB + go);
        }
        cp_commit();
    };

    float acc[4][8][4];
    #pragma unroll
    for (int mt = 0; mt < 4; mt++)
        #pragma unroll
        for (int nt = 0; nt < 8; nt++)
            #pragma unroll
            for (int q = 0; q < 4; q++) acc[mt][nt][q] = 0.f;

    load_stage(0, 0);
    load_stage(1, 1);
    load_stage(2, 2);

    const int matid = lane >> 3, lrow = lane & 7;

    for (int kt = 0; kt < KITERS; kt++) {
        const int s = kt % NSTG;
        cp_wait2();
        __syncthreads();
        if (kt + 3 < KITERS) load_stage(kt + 3, (kt + 3) % NSTG);

        const uint32_t sa = sbase + s*STG;
        #pragma unroll
        for (int h = 0; h < 2; h++) {        // two k16 halves of BK=32
            const int cbase = h*2;
            uint32_t ah[4][4];
            #pragma unroll
            for (int mt = 0; mt < 4; mt++) {
                int m = wm*64 + mt*16 + ((matid & 1) ? 8 : 0) + lrow;
                int c = cbase + (matid >> 1);
                ldmx4(ah[mt], sa + SA_H + sw_off(m, c));
            }
            uint32_t bf[4][4];
            #pragma unroll
            for (int np = 0; np < 4; np++) {
                int n = wn*64 + np*16 + ((matid >> 1) ? 8 : 0) + lrow;
                int c = cbase + (matid & 1);
                ldmx4(bf[np], sa + SB_H + sw_off(n, c));
            }
            #pragma unroll
            for (int mt = 0; mt < 4; mt++)
                #pragma unroll
                for (int nt = 0; nt < 8; nt++)
                    mma16816(acc[mt][nt], ah[mt], &bf[nt >> 1][(nt & 1)*2]);
        }
    }

    // epilogue: write fp16 pairs
    const int mrow = wm*64 + (lane >> 2);
    const int ncol = wn*64 + (lane & 3)*2;
    #pragma unroll
    for (int nt = 0; nt < 8; nt++) {
        const int col = ncol + nt*8;
        const float b0 = bias[n0 + col], b1 = bias[n0 + col + 1];
        #pragma unroll
        for (int mt = 0; mt < 4; mt++) {
            __half* o = g_projh + ((size_t)stepi*BT + m0 + mrow + mt*16)*CC + n0 + col;
            *reinterpret_cast<__half2*>(o) =
                __floats2half2_rn(acc[mt][nt][0] + b0, acc[mt][nt][1] + b1);
            *reinterpret_cast<__half2*>(o + 8*CC) =
                __floats2half2_rn(acc[mt][nt][2] + b0, acc[mt][nt][3] + b1);
        }
    }
}

// ============================ logits HMMA dot kernel ============================
// One block (256 thr, 8 warps) per (b, t2): logits[12x11] =
// proj[<=12][768] x targets[11][768]^T. Warp w covers K-range [w*96,(w+1)*96).
#define DROWB 1552
#define SP_OFF 0                           // 12 proj rows
#define ST_OFF (12*DROWB)                  // 16 target rows
#define SACC_OFF (ST_OFF + 16*DROWB)       // 8*256 floats
#define DOT_SMEM (SACC_OFF + 8*256*4)      // 51648

__global__ __launch_bounds__(256) void dot3_kernel(
    const int* __restrict__ neg, float* __restrict__ outp)
{
    extern __shared__ char dsm[];
    const uint32_t sbase = smem_u32(dsm);
    float* sAcc = reinterpret_cast<float*>(dsm + SACC_OFF);
    const int b  = blockIdx.y;
    const int t2 = blockIdx.x + 1;        // 1..1023
    const int tid = threadIdx.x;
    const int nvalid = (t2 < STEPS) ? t2 : STEPS;

    const uint4* yT4 = reinterpret_cast<const uint4*>(g_yTh);
    const uint4* pj4 = reinterpret_cast<const uint4*>(g_projh);

    uint4* sP4 = reinterpret_cast<uint4*>(dsm + SP_OFF);
    for (int idx = tid; idx < 12*96; idx += 256) {
        int i = idx / 96, q = idx - i*96;
        if (i < nvalid) {
            int t = t2 - 1 - i;
            sP4[i*97 + q] = __ldg(&pj4[((size_t)i*BT + (size_t)b*TT + t)*96 + q]);
        }
    }
    uint4* sT4 = reinterpret_cast<uint4*>(dsm + ST_OFF);
    for (int idx = tid; idx < 11*96; idx += 256) {
        int n = idx / 96, q = idx - n*96;
        int src = (n == 0) ? (b*TT + t2) : neg[b*(NNEG*TT) + (n-1)*TT + t2];
        sT4[n*97 + q] = __ldg(&yT4[(size_t)src*96 + q]);
    }
    __syncthreads();

    const int w = tid >> 5, lane = tid & 31;
    const int matid = lane >> 3, lrow = lane & 7;
    const uint32_t aBase = sbase + SP_OFF + (lane & 15)*DROWB + (lane >> 4)*16;
    const uint32_t bBase = sbase + ST_OFF + ((matid >> 1)*8 + lrow)*DROWB + (matid & 1)*16;

    float acc0[4] = {0.f, 0.f, 0.f, 0.f};
    float acc1[4] = {0.f, 0.f, 0.f, 0.f};
    #pragma unroll
    for (int j = 0; j < 6; j++) {
        const uint32_t koff = (w*6 + j)*32;
        uint32_t a[4], bq[4];
        ldmx4(a, aBase + koff);
        ldmx4(bq, bBase + koff);
        mma16816(acc0, a, &bq[0]);
        mma16816(acc1, a, &bq[2]);
    }

    {
        const int row = lane >> 2, col = (lane & 3)*2;
        float* sw_ = sAcc + w*256;
        sw_[row*16 + col]       = acc0[0];
        sw_[row*16 + col + 1]   = acc0[1];
        sw_[(row+8)*16 + col]     = acc0[2];
        sw_[(row+8)*16 + col + 1] = acc0[3];
        sw_[row*16 + 8 + col]     = acc1[0];
        sw_[row*16 + 8 + col + 1] = acc1[1];
        sw_[(row+8)*16 + 8 + col]     = acc1[2];
        sw_[(row+8)*16 + 8 + col + 1] = acc1[3];
    }
    __syncthreads();

    if (tid < 256) {
        const int idx = tid;
        const int i = idx >> 4, n = idx & 15;
        if (i < nvalid && n < COPIES) {
            float v = 0.f;
            #pragma unroll
            for (int s = 0; s < 8; s++) v += sAcc[s*256 + idx];
            const int t = t2 - 1 - i;
            const int off = 16*(1023*i - (i*(i-1))/2);
            outp[(size_t)(off + t*BB + b)*COPIES + n] = v;
        }
    }
}

// ============================ host ============================
extern "C" void kernel_launch(void* const* d_in, const int* in_sizes, int n_in,
                              void* d_out, int out_size) {
    const float* x    = (const float*)d_in[0];
    const float* y    = (const float*)d_in[1];
    const float* W    = (const float*)d_in[2];
    const float* bias = (const float*)d_in[3];
    const int*   neg  = (const int*)d_in[4];
    float* out = (float*)d_out;

    int total_rows = 0;
    for (int i = 0; i < STEPS; i++) total_rows += (TT - 1 - i) * BB;  // 195360
    size_t npred = (size_t)total_rows * COPIES;

    if ((size_t)out_size > npred)
        cudaMemsetAsync((char*)d_out + npred * 4, 0, ((size_t)out_size - npred) * 4);

    static bool attr_set = false;
    if (!attr_set) {
        cudaFuncSetAttribute(gemm_hmma_kernel,
                             cudaFuncAttributeMaxDynamicSharedMemorySize, SMEM_GEMM);
        cudaFuncSetAttribute(dot3_kernel,
                             cudaFuncAttributeMaxDynamicSharedMemorySize, DOT_SMEM);
        attr_set = true;
    }

    {   // fused x+y transpose -> fp16
        dim3 g(TT/32, CC/32, BB), blk(32, 8);
        pack_xy_kernel<<<g, blk>>>(x, y);
    }
    {   // W pack (fp16, coalesced smem transpose)
        dim3 g(CC/32, CC/32), blk(32, 8);
        pack_w_kernel<<<g, blk>>>(W);
    }
    {   // HMMA GEMM
        dim3 g(CC/BN, BT/BM, STEPS);   // (3, 128, 12)
        gemm_hmma_kernel<<<g, 256, SMEM_GEMM>>>(bias);
    }
    {   // logits via HMMA
        dim3 g(TT-1, BB);              // (1023, 16)
        dot3_kernel<<<g, 256, DOT_SMEM>>>(neg, out);
    }
}

// round 16
// speedup vs baseline: 1.1728x; 1.1728x over previous
#include <cuda_runtime.h>
#include <cuda_fp16.h>
#include <cstdint>

#define BB 16
#define CC 768
#define TT 1024
#define STEPS 12
#define NNEG 10
#define COPIES 11
#define BT (BB*TT)  // 16384

// ---- scratch (static device globals; no runtime allocation) ----
__device__ __half g_yTh[(size_t)BB*TT*CC];        // [b][t][c] fp16
__device__ __half g_projh[(size_t)STEPS*BT*CC];   // [i][m][d] fp16
__device__ __half g_xh[(size_t)BT*CC];            // [m][c] fp16
__device__ __half g_wh[(size_t)STEPS*CC*CC];      // [(i*768+d)][c] fp16

// ============================ asm helpers ============================
__device__ __forceinline__ uint32_t smem_u32(const void* p) {
    uint32_t a;
    asm("{ .reg .u64 t; cvta.to.shared.u64 t, %1; cvt.u32.u64 %0, t; }" : "=r"(a) : "l"(p));
    return a;
}

__device__ __forceinline__ void cp_async16(uint32_t saddr, const void* gaddr) {
    asm volatile("cp.async.cg.shared.global [%0], [%1], 16;" :: "r"(saddr), "l"(gaddr));
}
__device__ __forceinline__ void cp_commit() {
    asm volatile("cp.async.commit_group;" ::: "memory");
}
__device__ __forceinline__ void cp_wait2() {
    asm volatile("cp.async.wait_group 2;" ::: "memory");
}

__device__ __forceinline__ void ldmx4(uint32_t* r, uint32_t addr) {
    asm volatile("ldmatrix.sync.aligned.m8n8.x4.shared.b16 {%0,%1,%2,%3}, [%4];"
        : "=r"(r[0]), "=r"(r[1]), "=r"(r[2]), "=r"(r[3]) : "r"(addr));
}

__device__ __forceinline__ void mma16816(float* d, const uint32_t* a, const uint32_t* b) {
    asm volatile("mma.sync.aligned.m16n8k16.row.col.f32.f16.f16.f32 "
        "{%0,%1,%2,%3}, {%4,%5,%6,%7}, {%8,%9}, {%0,%1,%2,%3};"
        : "+f"(d[0]), "+f"(d[1]), "+f"(d[2]), "+f"(d[3])
        : "r"(a[0]), "r"(a[1]), "r"(a[2]), "r"(a[3]), "r"(b[0]), "r"(b[1]));
}

// swizzled byte offset for a (row, 16B-chunk) of a [rows][32] fp16 tile
__device__ __forceinline__ uint32_t sw_off(int r, int c) {
    uint32_t bo = r*64 + c*16;
    return bo ^ (((bo >> 7) & 7) << 4);
}

// ============================ prepack kernels ============================
// fused x+y transpose -> fp16 [b][t][c]
__global__ void pack_xy_kernel(const float* __restrict__ x, const float* __restrict__ y) {
    __shared__ float tx_[32][33];
    __shared__ float ty_[32][33];
    int b = blockIdx.z, c0 = blockIdx.y * 32, t0 = blockIdx.x * 32;
    int tx = threadIdx.x, ty = threadIdx.y;
    #pragma unroll
    for (int j = 0; j < 32; j += 8) {
        size_t src = ((size_t)b*CC + c0 + ty + j)*TT + t0 + tx;
        tx_[ty + j][tx] = x[src];
        ty_[ty + j][tx] = y[src];
    }
    __syncthreads();
    #pragma unroll
    for (int j = 0; j < 32; j += 8) {
        size_t dst = ((size_t)b*TT + t0 + ty + j)*CC + c0 + tx;
        g_xh[dst]  = __float2half_rn(tx_[tx][ty + j]);
        g_yTh[dst] = __float2half_rn(ty_[tx][ty + j]);
    }
}

// W[c][d][i] -> g_wh[(i*768+d)][c], coalesced via padded smem transpose.
__global__ void pack_w_kernel(const float* __restrict__ W) {
    __shared__ __half sw[32][33][STEPS];
    const int c0 = blockIdx.x * 32, d0 = blockIdx.y * 32;
    const int tx = threadIdx.x, ty = threadIdx.y;
    #pragma unroll
    for (int j = 0; j < 4; j++) {
        int cl = ty + j*8;
        const float4* src = reinterpret_cast<const float4*>(
            W + ((size_t)(c0 + cl)*CC + d0 + tx)*STEPS);
        float4 a = src[0], bq = src[1], cq = src[2];
        __half* o = &sw[cl][tx][0];
        o[0] = __float2half_rn(a.x);  o[1] = __float2half_rn(a.y);
        o[2] = __float2half_rn(a.z);  o[3] = __float2half_rn(a.w);
        o[4] = __float2half_rn(bq.x); o[5] = __float2half_rn(bq.y);
        o[6] = __float2half_rn(bq.z); o[7] = __float2half_rn(bq.w);
        o[8] = __float2half_rn(cq.x); o[9] = __float2half_rn(cq.y);
        o[10] = __float2half_rn(cq.z); o[11] = __float2half_rn(cq.w);
    }
    __syncthreads();
    #pragma unroll
    for (int i = 0; i < STEPS; i++)
        #pragma unroll
        for (int j = 0; j < 4; j++) {
            int dl = ty + j*8;
            g_wh[((size_t)i*CC + d0 + dl)*CC + c0 + tx] = sw[tx][dl][i];
        }
}

// ============================ HMMA GEMM ============================
// Single-pass fp16: proj = x*w (+bias), output fp16.  (round-14 proven config)
#define BM 128
#define BN 128
#define BK 32
#define KITERS (CC/BK)   // 24
#define TILE_B (BM*BK*2) // 8192 bytes per sub-tile
#define SA_H 0
#define SB_H (TILE_B)
#define STG  (2*TILE_B)  // 16384 per stage
#define NSTG 4
#define SMEM_GEMM (NSTG*STG) // 65536

__global__ __launch_bounds__(256, 2) void gemm_hmma_kernel(const float* __restrict__ bias)
{
    extern __shared__ char smem[];
    const uint32_t sbase = smem_u32(smem);
    const int tid = threadIdx.x;
    const int wid = tid >> 5, lane = tid & 31;
    const int n0 = blockIdx.x * BN;
    const int m0 = blockIdx.y * BM;
    const int stepi = blockIdx.z;
    const int wm = wid >> 2;     // 0..1
    const int wn = wid & 3;      // 0..3

    const __half* gA = g_xh + (size_t)m0*CC;
    const __half* gB = g_wh + ((size_t)stepi*CC + n0)*CC;

    const int lr0 = tid >> 2, lc = tid & 3;

    auto load_stage = [&](int kt, int s) {
        const int k0 = kt * BK;
        const uint32_t sa = sbase + s*STG;
        #pragma unroll
        for (int e = 0; e < 2; e++) {
            int r = lr0 + e*64;
            uint32_t so = sw_off(r, lc);
            size_t go = (size_t)r*CC + k0 + lc*8;
            cp_async16(sa + SA_H + so, gA + go);
            cp_async16(sa + SB_H + so, gB + go);
        }
        cp_commit();
    };

    float acc[4][4][4];
    #pragma unroll
    for (int mt = 0; mt < 4; mt++)
        #pragma unroll
        for (int nt = 0; nt < 4; nt++)
            #pragma unroll
            for (int q = 0; q < 4; q++) acc[mt][nt][q] = 0.f;

    load_stage(0, 0);
    load_stage(1, 1);
    load_stage(2, 2);

    const int matid = lane >> 3, lrow = lane & 7;

    for (int kt = 0; kt < KITERS; kt++) {
        const int s = kt % NSTG;
        cp_wait2();
        __syncthreads();
        if (kt + 3 < KITERS) load_stage(kt + 3, (kt + 3) % NSTG);

        const uint32_t sa = sbase + s*STG;
        #pragma unroll
        for (int h = 0; h < 2; h++) {
            const int cbase = h*2;
            uint32_t ah[4][4];
            #pragma unroll
            for (int mt = 0; mt < 4; mt++) {
                int m = wm*64 + mt*16 + ((matid & 1) ? 8 : 0) + lrow;
                int c = cbase + (matid >> 1);
                ldmx4(ah[mt], sa + SA_H + sw_off(m, c));
            }
            uint32_t bf[2][4];
            #pragma unroll
            for (int np = 0; np < 2; np++) {
                int n = wn*32 + np*16 + ((matid >> 1) ? 8 : 0) + lrow;
                int c = cbase + (matid & 1);
                ldmx4(bf[np], sa + SB_H + sw_off(n, c));
            }
            #pragma unroll
            for (int mt = 0; mt < 4; mt++)
                #pragma unroll
                for (int nt = 0; nt < 4; nt++)
                    mma16816(acc[mt][nt], ah[mt], &bf[nt >> 1][(nt & 1)*2]);
        }
    }

    const int mrow = wm*64 + (lane >> 2);
    const int ncol = wn*32 + (lane & 3)*2;
    #pragma unroll
    for (int nt = 0; nt < 4; nt++) {
        const int col = ncol + nt*8;
        const float b0 = bias[n0 + col], b1 = bias[n0 + col + 1];
        #pragma unroll
        for (int mt = 0; mt < 4; mt++) {
            __half* o = g_projh + ((size_t)stepi*BT + m0 + mrow + mt*16)*CC + n0 + col;
            *reinterpret_cast<__half2*>(o) =
                __floats2half2_rn(acc[mt][nt][0] + b0, acc[mt][nt][1] + b1);
            *reinterpret_cast<__half2*>(o + 8*CC) =
                __floats2half2_rn(acc[mt][nt][2] + b0, acc[mt][nt][3] + b1);
        }
    }
}

// ============================ logits HMMA dot kernel ============================
// One block (384 thr, 12 warps) per (b, t2): logits[12x11] =
// proj[<=12][768] x targets[11][768]^T. Warp w covers K-range [w*64,(w+1)*64).
// Rows padded to 1552B (97x16B -> row r hits 16B-group r mod 8: conflict-free
// ldmatrix). Proj region 12 rows; target region 16 rows so ldmatrix row-15
// addresses stay in-bounds (rows 11-15 garbage feed only discarded outputs).
#define DROWB 1552
#define SP_OFF 0                           // 12 proj rows
#define ST_OFF (12*DROWB)                  // 16 target rows
#define SACC_OFF (ST_OFF + 16*DROWB)       // 12*256 floats
#define DOT_SMEM (SACC_OFF + 12*256*4)     // 55744

__global__ __launch_bounds__(384) void dot3_kernel(
    const int* __restrict__ neg, float* __restrict__ outp)
{
    extern __shared__ char dsm[];
    const uint32_t sbase = smem_u32(dsm);
    float* sAcc = reinterpret_cast<float*>(dsm + SACC_OFF);
    const int b  = blockIdx.y;
    const int t2 = blockIdx.x + 1;        // 1..1023
    const int tid = threadIdx.x;
    const int nvalid = (t2 < STEPS) ? t2 : STEPS;

    const uint4* yT4 = reinterpret_cast<const uint4*>(g_yTh);   // 8 halves each
    const uint4* pj4 = reinterpret_cast<const uint4*>(g_projh);

    // stage proj rows (i < nvalid); 96 uint4 per row
    uint4* sP4 = reinterpret_cast<uint4*>(dsm + SP_OFF);
    for (int idx = tid; idx < 12*96; idx += 384) {
        int i = idx / 96, q = idx - i*96;
        if (i < nvalid) {
            int t = t2 - 1 - i;
            sP4[i*97 + q] = __ldg(&pj4[((size_t)i*BT + (size_t)b*TT + t)*96 + q]);
        }
    }
    // stage 11 target rows
    uint4* sT4 = reinterpret_cast<uint4*>(dsm + ST_OFF);
    for (int idx = tid; idx < 11*96; idx += 384) {
        int n = idx / 96, q = idx - n*96;
        int src = (n == 0) ? (b*TT + t2) : neg[b*(NNEG*TT) + (n-1)*TT + t2];
        sT4[n*97 + q] = __ldg(&yT4[(size_t)src*96 + q]);
    }
    __syncthreads();

    const int w = tid >> 5, lane = tid & 31;
    const int matid = lane >> 3, lrow = lane & 7;
    // A (proj, m16xk16): row = lane%16, 16B chunk = lane/16
    const uint32_t aBase = sbase + SP_OFF + (lane & 15)*DROWB + (lane >> 4)*16;
    // B (targets, n16xk16): n row = (matid>>1)*8+lrow, chunk = matid&1
    const uint32_t bBase = sbase + ST_OFF + ((matid >> 1)*8 + lrow)*DROWB + (matid & 1)*16;

    float acc0[4] = {0.f, 0.f, 0.f, 0.f};
    float acc1[4] = {0.f, 0.f, 0.f, 0.f};
    #pragma unroll
    for (int j = 0; j < 4; j++) {
        const uint32_t koff = (w*4 + j)*32;   // 16 channels = 32 bytes
        uint32_t a[4], bq[4];
        ldmx4(a, aBase + koff);
        ldmx4(bq, bBase + koff);
        mma16816(acc0, a, &bq[0]);   // n copies 0..7
        mma16816(acc1, a, &bq[2]);   // n copies 8..15
    }

    // write partials: D layout m16n8: d0,d1 -> (row, col..col+1); d2,d3 -> row+8
    {
        const int row = lane >> 2, col = (lane & 3)*2;
        float* sw_ = sAcc + w*256;
        sw_[row*16 + col]       = acc0[0];
        sw_[row*16 + col + 1]   = acc0[1];
        sw_[(row+8)*16 + col]     = acc0[2];
        sw_[(row+8)*16 + col + 1] = acc0[3];
        sw_[row*16 + 8 + col]     = acc1[0];
        sw_[row*16 + 8 + col + 1] = acc1[1];
        sw_[(row+8)*16 + 8 + col]     = acc1[2];
        sw_[(row+8)*16 + 8 + col + 1] = acc1[3];
    }
    __syncthreads();

    // reduce 12 warps and write valid (i, n)
    if (tid < 256) {
        const int idx = tid;
        const int i = idx >> 4, n = idx & 15;
        if (i < nvalid && n < COPIES) {
            float v = 0.f;
            #pragma unroll
            for (int s = 0; s < 12; s++) v += sAcc[s*256 + idx];
            const int t = t2 - 1 - i;
            const int off = 16*(1023*i - (i*(i-1))/2);
            outp[(size_t)(off + t*BB + b)*COPIES + n] = v;
        }
    }
}

// ============================ host ============================
extern "C" void kernel_launch(void* const* d_in, const int* in_sizes, int n_in,
                              void* d_out, int out_size) {
    const float* x    = (const float*)d_in[0];
    const float* y    = (const float*)d_in[1];
    const float* W    = (const float*)d_in[2];
    const float* bias = (const float*)d_in[3];
    const int*   neg  = (const int*)d_in[4];
    float* out = (float*)d_out;

    int total_rows = 0;
    for (int i = 0; i < STEPS; i++) total_rows += (TT - 1 - i) * BB;  // 195360
    size_t npred = (size_t)total_rows * COPIES;

    if ((size_t)out_size > npred)
        cudaMemsetAsync((char*)d_out + npred * 4, 0, ((size_t)out_size - npred) * 4);

    static bool attr_set = false;
    if (!attr_set) {
        cudaFuncSetAttribute(gemm_hmma_kernel,
                             cudaFuncAttributeMaxDynamicSharedMemorySize, SMEM_GEMM);
        cudaFuncSetAttribute(dot3_kernel,
                             cudaFuncAttributeMaxDynamicSharedMemorySize, DOT_SMEM);
        attr_set = true;
    }

    {   // fused x+y transpose -> fp16
        dim3 g(TT/32, CC/32, BB), blk(32, 8);
        pack_xy_kernel<<<g, blk>>>(x, y);
    }
    {   // W pack (fp16, coalesced smem transpose)
        dim3 g(CC/32, CC/32), blk(32, 8);
        pack_w_kernel<<<g, blk>>>(W);
    }
    {   // HMMA GEMM
        dim3 g(CC/BN, BT/BM, STEPS);   // (6, 128, 12)
        gemm_hmma_kernel<<<g, 256, SMEM_GEMM>>>(bias);
    }
    {   // logits via HMMA
        dim3 g(TT-1, BB);              // (1023, 16)
        dot3_kernel<<<g, 384, DOT_SMEM>>>(neg, out);
    }
}